// round 1
// baseline (speedup 1.0000x reference)
#include <cuda_runtime.h>
#include <cstdint>

#define ROWS 8192
#define KDIM 128
#define NPER 82        // int(8192 * 1 / 100) + 1

// Scratch (device globals: no allocation allowed)
__device__ float g_r[ROWS];    // dot(x1_i, x2_i) / ||x2_i||
__device__ float g_n2[ROWS];   // ||x2_j||
__device__ int   g_cnt[ROWS];  // per-row count of strictly-greater sims

// ---------------------------------------------------------------------------
// Kernel A: per-row thresholds + zero the counters (runs every replay).
// One warp per row; lane holds 4 contiguous floats (float4).
// ---------------------------------------------------------------------------
__global__ void prep_kernel(const float* __restrict__ x1,
                            const float* __restrict__ x2) {
    int warp = (blockIdx.x * blockDim.x + threadIdx.x) >> 5;
    int lane = threadIdx.x & 31;
    if (warp >= ROWS) return;
    float4 a = *(const float4*)(x1 + warp * KDIM + lane * 4);
    float4 b = *(const float4*)(x2 + warp * KDIM + lane * 4);
    float s2 = b.x * b.x + b.y * b.y + b.z * b.z + b.w * b.w;
    float d  = a.x * b.x + a.y * b.y + a.z * b.z + a.w * b.w;
    #pragma unroll
    for (int o = 16; o > 0; o >>= 1) {
        s2 += __shfl_down_sync(0xffffffffu, s2, o);
        d  += __shfl_down_sync(0xffffffffu, d,  o);
    }
    if (lane == 0) {
        float n2 = sqrtf(s2);
        g_n2[warp]  = n2;
        g_r[warp]   = d / n2;
        g_cnt[warp] = 0;
    }
}

// ---------------------------------------------------------------------------
// Kernel B: counting GEMM. BM=BN=128, K chunked by 32, 512 threads,
// 8x4 micro-tile accumulated as packed f32x2 over k-pairs (fma.rn.f32x2).
// SMEM layout: [k2][2*row + parity], row length 256 padded to 260 floats.
// ---------------------------------------------------------------------------
#define SROW 260

__global__ __launch_bounds__(512, 1)
void count_kernel(const float* __restrict__ x1,
                  const float* __restrict__ x2) {
    __shared__ float As[16 * SROW];
    __shared__ float Bs[16 * SROW];

    const int tid = threadIdx.x;
    const int tx  = tid & 31;   // n-group: cols j0 + 4*tx .. +3
    const int ty  = tid >> 5;   // m-group (== warp id): rows i0 + 8*ty .. +7
    const int i0  = blockIdx.y * 128;
    const int j0  = blockIdx.x * 128;

    unsigned long long acc[8][4];
    #pragma unroll
    for (int m = 0; m < 8; m++)
        #pragma unroll
        for (int n = 0; n < 4; n++) acc[m][n] = 0ull;

    for (int kc = 0; kc < KDIM; kc += 32) {
        __syncthreads();
        // Load 128x32 chunk of each matrix; pack k-pairs interleaved per row.
        #pragma unroll
        for (int s = 0; s < 2; s++) {
            int f   = tid + s * 512;     // float4 index in [0,1024)
            int row = f >> 3;
            int kq  = f & 7;
            float4 v = *(const float4*)(x1 + (i0 + row) * KDIM + kc + kq * 4);
            *(float2*)(As + (2 * kq    ) * SROW + 2 * row) = make_float2(v.x, v.y);
            *(float2*)(As + (2 * kq + 1) * SROW + 2 * row) = make_float2(v.z, v.w);
            float4 w = *(const float4*)(x2 + (j0 + row) * KDIM + kc + kq * 4);
            *(float2*)(Bs + (2 * kq    ) * SROW + 2 * row) = make_float2(w.x, w.y);
            *(float2*)(Bs + (2 * kq + 1) * SROW + 2 * row) = make_float2(w.z, w.w);
        }
        __syncthreads();

        #pragma unroll
        for (int k2 = 0; k2 < 16; k2++) {
            const double2* ap = (const double2*)(As + k2 * SROW + 16 * ty);
            const double2* bp = (const double2*)(Bs + k2 * SROW + 8  * tx);
            unsigned long long A[8], B[4];
            #pragma unroll
            for (int q = 0; q < 4; q++) {
                double2 d = ap[q];                      // LDS.128, broadcast
                A[2 * q]     = __double_as_longlong(d.x);
                A[2 * q + 1] = __double_as_longlong(d.y);
            }
            #pragma unroll
            for (int q = 0; q < 2; q++) {
                double2 d = bp[q];                      // LDS.128, conflict-free
                B[2 * q]     = __double_as_longlong(d.x);
                B[2 * q + 1] = __double_as_longlong(d.y);
            }
            #pragma unroll
            for (int m = 0; m < 8; m++)
                #pragma unroll
                for (int n = 0; n < 4; n++)
                    asm("fma.rn.f32x2 %0, %1, %2, %0;"
                        : "+l"(acc[m][n]) : "l"(A[m]), "l"(B[n]));
        }
    }

    // Epilogue: compare dot > r_i * n2_j, exclude j==i, reduce per row.
    const int ib = i0 + ty * 8;
    const int jb = j0 + tx * 4;
    float nn[4];
    #pragma unroll
    for (int n = 0; n < 4; n++) nn[n] = g_n2[jb + n];

    #pragma unroll
    for (int m = 0; m < 8; m++) {
        float r = g_r[ib + m];
        int c = 0;
        #pragma unroll
        for (int n = 0; n < 4; n++) {
            unsigned long long v = acc[m][n];
            float lo = __uint_as_float((unsigned)(v & 0xffffffffull));
            float hi = __uint_as_float((unsigned)(v >> 32));
            float s  = lo + hi;
            c += ((s > r * nn[n]) && ((ib + m) != (jb + n))) ? 1 : 0;
        }
        c = (int)__reduce_add_sync(0xffffffffu, (unsigned)c);
        if (tx == 0) atomicAdd(&g_cnt[ib + m], c);
    }
}

// ---------------------------------------------------------------------------
// Kernel C: mean of (count < NPER)
// ---------------------------------------------------------------------------
__global__ void finalize_kernel(float* __restrict__ out) {
    __shared__ int sh[256];
    int t = threadIdx.x;
    int c = 0;
    for (int i = t; i < ROWS; i += 256) c += (g_cnt[i] < NPER) ? 1 : 0;
    sh[t] = c;
    __syncthreads();
    #pragma unroll
    for (int s = 128; s > 0; s >>= 1) {
        if (t < s) sh[t] += sh[t + s];
        __syncthreads();
    }
    if (t == 0) out[0] = (float)sh[0] / (float)ROWS;
}

// ---------------------------------------------------------------------------
extern "C" void kernel_launch(void* const* d_in, const int* in_sizes, int n_in,
                              void* d_out, int out_size) {
    const float* x1 = (const float*)d_in[0];
    const float* x2 = (const float*)d_in[1];
    float* out = (float*)d_out;
    (void)in_sizes; (void)n_in; (void)out_size;

    prep_kernel<<<ROWS / 8, 256>>>(x1, x2);          // 8 warps/block
    count_kernel<<<dim3(64, 64), 512>>>(x1, x2);
    finalize_kernel<<<1, 256>>>(out);
}

// round 6
// speedup vs baseline: 3.1333x; 3.1333x over previous
#include <cuda_runtime.h>
#include <cuda_fp16.h>
#include <cstdint>

#define ROWS 8192
#define KDIM 128
#define NPER 82        // int(8192 * 1 / 100) + 1

// Scratch (device globals: no allocation allowed)
__device__ float  g_r[ROWS];            // dot(x1_i, x2_i) / ||x2_i||
__device__ float  g_n2[ROWS];           // ||x2_j||
__device__ int    g_cnt[ROWS];          // per-row count of strictly-greater sims
__device__ __half g_x1h[ROWS * KDIM];   // fp16 hi/lo split of inputs
__device__ __half g_x1l[ROWS * KDIM];
__device__ __half g_x2h[ROWS * KDIM];
__device__ __half g_x2l[ROWS * KDIM];

__device__ __forceinline__ uint32_t smem_u32(const void* p) {
    uint32_t a;
    asm("{ .reg .u64 t; cvta.to.shared.u64 t, %1; cvt.u32.u64 %0, t; }"
        : "=r"(a) : "l"(p));
    return a;
}

#define LDSM_X4(r0, r1, r2, r3, addr) \
    asm volatile("ldmatrix.sync.aligned.m8n8.x4.shared.b16 {%0,%1,%2,%3}, [%4];" \
                 : "=r"(r0), "=r"(r1), "=r"(r2), "=r"(r3) : "r"(addr))

#define MMA_16816(c, a, b0, b1) \
    asm volatile("mma.sync.aligned.m16n8k16.row.col.f32.f16.f16.f32 " \
                 "{%0,%1,%2,%3}, {%4,%5,%6,%7}, {%8,%9}, {%0,%1,%2,%3};" \
                 : "+f"((c)[0]), "+f"((c)[1]), "+f"((c)[2]), "+f"((c)[3]) \
                 : "r"((a)[0]), "r"((a)[1]), "r"((a)[2]), "r"((a)[3]), \
                   "r"(b0), "r"(b1))

#define CP_ASYNC16(dst, src) \
    asm volatile("cp.async.cg.shared.global [%0], [%1], 16;" :: "r"(dst), "l"(src))
#define CP_COMMIT() asm volatile("cp.async.commit_group;" ::: "memory")

// ---------------------------------------------------------------------------
// Kernel A: thresholds + counter zero + fp16 hi/lo conversion of both inputs.
// One warp per row; lane holds 4 contiguous floats.
// ---------------------------------------------------------------------------
__global__ void prep_kernel(const float* __restrict__ x1,
                            const float* __restrict__ x2) {
    int warp = (blockIdx.x * blockDim.x + threadIdx.x) >> 5;
    int lane = threadIdx.x & 31;
    if (warp >= ROWS) return;
    float4 a = *(const float4*)(x1 + warp * KDIM + lane * 4);
    float4 b = *(const float4*)(x2 + warp * KDIM + lane * 4);

    // fp16 hi/lo split, stored to global scratch
    int base = warp * KDIM + lane * 4;
    {
        __half h0 = __float2half_rn(a.x), h1 = __float2half_rn(a.y);
        __half h2 = __float2half_rn(a.z), h3 = __float2half_rn(a.w);
        *(half2*)(g_x1h + base)     = __halves2half2(h0, h1);
        *(half2*)(g_x1h + base + 2) = __halves2half2(h2, h3);
        __half l0 = __float2half_rn(a.x - __half2float(h0));
        __half l1 = __float2half_rn(a.y - __half2float(h1));
        __half l2 = __float2half_rn(a.z - __half2float(h2));
        __half l3 = __float2half_rn(a.w - __half2float(h3));
        *(half2*)(g_x1l + base)     = __halves2half2(l0, l1);
        *(half2*)(g_x1l + base + 2) = __halves2half2(l2, l3);
    }
    {
        __half h0 = __float2half_rn(b.x), h1 = __float2half_rn(b.y);
        __half h2 = __float2half_rn(b.z), h3 = __float2half_rn(b.w);
        *(half2*)(g_x2h + base)     = __halves2half2(h0, h1);
        *(half2*)(g_x2h + base + 2) = __halves2half2(h2, h3);
        __half l0 = __float2half_rn(b.x - __half2float(h0));
        __half l1 = __float2half_rn(b.y - __half2float(h1));
        __half l2 = __float2half_rn(b.z - __half2float(h2));
        __half l3 = __float2half_rn(b.w - __half2float(h3));
        *(half2*)(g_x2l + base)     = __halves2half2(l0, l1);
        *(half2*)(g_x2l + base + 2) = __halves2half2(l2, l3);
    }

    float s2 = b.x * b.x + b.y * b.y + b.z * b.z + b.w * b.w;
    float d  = a.x * b.x + a.y * b.y + a.z * b.z + a.w * b.w;
    #pragma unroll
    for (int o = 16; o > 0; o >>= 1) {
        s2 += __shfl_down_sync(0xffffffffu, s2, o);
        d  += __shfl_down_sync(0xffffffffu, d,  o);
    }
    if (lane == 0) {
        float n2 = sqrtf(s2);
        g_n2[warp]  = n2;
        g_r[warp]   = d / n2;
        g_cnt[warp] = 0;
    }
}

// ---------------------------------------------------------------------------
// Kernel B: counting GEMM via mma.sync m16n8k16 fp16, 3-term hi/lo split.
// BM=BN=128 tile, K streamed in 4 chunks of 32 with cp.async double buffer.
// SMEM chunk buffer (32 KB): A_hi[128][32], A_lo, B_hi[128][32], B_lo fp16,
// rows 64B with 16B-slot swizzle  slot ^= (row>>1)&3  (conflict-free LDSM).
// 8 warps, warp tile 64x32 (2x4 warp grid), mma tiles 4(m) x 4(n).
// ---------------------------------------------------------------------------
#define BUF_SZ 32768
#define SMEM_TOTAL (2 * BUF_SZ)

__device__ __forceinline__ void load_chunk(uint32_t bufb, int i0, int j0,
                                           int kc, int tid) {
    const int s  = tid & 3;        // 16B slot within 64B chunk-row
    const int rh = tid >> 2;       // 0..63
    #pragma unroll
    for (int q = 0; q < 8; q++) {
        const int arr = q >> 1;                 // 0:A_hi 1:A_lo 2:B_hi 3:B_lo
        const int row = ((q & 1) << 6) + rh;    // 0..127
        const __half* g = (arr == 0) ? g_x1h : (arr == 1) ? g_x1l
                        : (arr == 2) ? g_x2h : g_x2l;
        const int grow = ((arr < 2) ? i0 : j0) + row;
        const __half* src = g + grow * KDIM + kc + s * 8;
        uint32_t dst = bufb + arr * 8192 + row * 64
                     + ((s ^ ((row >> 1) & 3)) << 4);
        CP_ASYNC16(dst, src);
    }
}

__device__ __forceinline__ void compute_chunk(uint32_t bufb, int wm, int wn,
                                              int l, float acc[4][4][4]) {
    const int lg = l >> 3, lr = l & 7;
    #pragma unroll
    for (int t = 0; t < 2; t++) {               // two k16 steps per chunk
        uint32_t ah[4][4], al[4][4];
        #pragma unroll
        for (int tm = 0; tm < 4; tm++) {
            const int row  = wm * 64 + tm * 16 + ((lg & 1) << 3) + lr;
            const int slot = 2 * t + (lg >> 1);
            const uint32_t off = row * 64 + ((slot ^ ((row >> 1) & 3)) << 4);
            LDSM_X4(ah[tm][0], ah[tm][1], ah[tm][2], ah[tm][3], bufb + off);
            LDSM_X4(al[tm][0], al[tm][1], al[tm][2], al[tm][3], bufb + 8192 + off);
        }
        #pragma unroll
        for (int p = 0; p < 2; p++) {           // n-tile pairs (2p, 2p+1)
            const int row  = wn * 32 + p * 16 + ((lg >> 1) << 3) + lr;
            const int slot = 2 * t + (lg & 1);
            const uint32_t off = row * 64 + ((slot ^ ((row >> 1) & 3)) << 4);
            uint32_t bh[4], bl[4];
            LDSM_X4(bh[0], bh[1], bh[2], bh[3], bufb + 16384 + off);
            LDSM_X4(bl[0], bl[1], bl[2], bl[3], bufb + 24576 + off);
            #pragma unroll
            for (int tm = 0; tm < 4; tm++) {
                MMA_16816(acc[tm][2 * p],     ah[tm], bh[0], bh[1]);
                MMA_16816(acc[tm][2 * p],     ah[tm], bl[0], bl[1]);
                MMA_16816(acc[tm][2 * p],     al[tm], bh[0], bh[1]);
                MMA_16816(acc[tm][2 * p + 1], ah[tm], bh[2], bh[3]);
                MMA_16816(acc[tm][2 * p + 1], ah[tm], bl[2], bl[3]);
                MMA_16816(acc[tm][2 * p + 1], al[tm], bh[2], bh[3]);
            }
        }
    }
}

__global__ __launch_bounds__(256, 1)
void count_kernel() {
    extern __shared__ char smem[];
    const uint32_t sb = smem_u32(smem);
    const int tid = threadIdx.x;
    const int l   = tid & 31;
    const int wid = tid >> 5;
    const int wm  = wid >> 2;        // 0..1  (64-row m slab)
    const int wn  = wid & 3;         // 0..3  (32-col n slab)
    const int i0  = blockIdx.y * 128;
    const int j0  = blockIdx.x * 128;

    float acc[4][4][4];
    #pragma unroll
    for (int a = 0; a < 4; a++)
        #pragma unroll
        for (int b = 0; b < 4; b++)
            #pragma unroll
            for (int c = 0; c < 4; c++) acc[a][b][c] = 0.f;

    // pipeline prologue: chunks 0 and 1 in flight
    load_chunk(sb,          i0, j0, 0,  tid); CP_COMMIT();
    load_chunk(sb + BUF_SZ, i0, j0, 32, tid); CP_COMMIT();

    #pragma unroll
    for (int c = 0; c < 4; c++) {
        if (c < 3) asm volatile("cp.async.wait_group 1;" ::: "memory");
        else       asm volatile("cp.async.wait_group 0;" ::: "memory");
        __syncthreads();
        compute_chunk(sb + (c & 1) * BUF_SZ, wm, wn, l, acc);
        __syncthreads();
        if (c < 2) {
            load_chunk(sb + (c & 1) * BUF_SZ, i0, j0, (c + 2) * 32, tid);
            CP_COMMIT();
        }
    }

    // Epilogue: compare dot > r_i * n2_j, exclude diagonal, count per row.
    float na[4], nb[4];
    #pragma unroll
    for (int tn = 0; tn < 4; tn++) {
        const int jb = j0 + wn * 32 + tn * 8 + ((l & 3) << 1);
        na[tn] = __ldg(&g_n2[jb]);
        nb[tn] = __ldg(&g_n2[jb + 1]);
    }
    #pragma unroll
    for (int tm = 0; tm < 4; tm++) {
        const int r0 = i0 + wm * 64 + tm * 16 + (l >> 2);
        const int r1 = r0 + 8;
        const float th0 = __ldg(&g_r[r0]);
        const float th1 = __ldg(&g_r[r1]);
        int c0 = 0, c1 = 0;
        #pragma unroll
        for (int tn = 0; tn < 4; tn++) {
            const int jb = j0 + wn * 32 + tn * 8 + ((l & 3) << 1);
            c0 += (acc[tm][tn][0] > th0 * na[tn] && jb     != r0) ? 1 : 0;
            c0 += (acc[tm][tn][1] > th0 * nb[tn] && jb + 1 != r0) ? 1 : 0;
            c1 += (acc[tm][tn][2] > th1 * na[tn] && jb     != r1) ? 1 : 0;
            c1 += (acc[tm][tn][3] > th1 * nb[tn] && jb + 1 != r1) ? 1 : 0;
        }
        c0 += __shfl_xor_sync(0xffffffffu, c0, 1);
        c0 += __shfl_xor_sync(0xffffffffu, c0, 2);
        c1 += __shfl_xor_sync(0xffffffffu, c1, 1);
        c1 += __shfl_xor_sync(0xffffffffu, c1, 2);
        if ((l & 3) == 0) {
            atomicAdd(&g_cnt[r0], c0);
            atomicAdd(&g_cnt[r1], c1);
        }
    }
}

// ---------------------------------------------------------------------------
// Kernel C: mean of (count < NPER)
// ---------------------------------------------------------------------------
__global__ void finalize_kernel(float* __restrict__ out) {
    __shared__ int sh[256];
    int t = threadIdx.x;
    int c = 0;
    for (int i = t; i < ROWS; i += 256) c += (g_cnt[i] < NPER) ? 1 : 0;
    sh[t] = c;
    __syncthreads();
    #pragma unroll
    for (int s = 128; s > 0; s >>= 1) {
        if (t < s) sh[t] += sh[t + s];
        __syncthreads();
    }
    if (t == 0) out[0] = (float)sh[0] / (float)ROWS;
}

// ---------------------------------------------------------------------------
extern "C" void kernel_launch(void* const* d_in, const int* in_sizes, int n_in,
                              void* d_out, int out_size) {
    const float* x1 = (const float*)d_in[0];
    const float* x2 = (const float*)d_in[1];
    float* out = (float*)d_out;
    (void)in_sizes; (void)n_in; (void)out_size;

    cudaFuncSetAttribute(count_kernel,
                         cudaFuncAttributeMaxDynamicSharedMemorySize, SMEM_TOTAL);

    prep_kernel<<<ROWS / 8, 256>>>(x1, x2);
    count_kernel<<<dim3(64, 64), 256, SMEM_TOTAL>>>();
    finalize_kernel<<<1, 256>>>(out);
}

// round 7
// speedup vs baseline: 3.1794x; 1.0147x over previous
#include <cuda_runtime.h>
#include <cuda_fp16.h>
#include <cstdint>

#define ROWS 8192
#define KDIM 128
#define NPER 82        // int(8192 * 1 / 100) + 1

// Scratch (device globals: no allocation allowed)
__device__ float  g_r[ROWS];            // dot(x1_i, x2_i) / ||x2_i||
__device__ float  g_n2[ROWS];           // ||x2_j||
__device__ int    g_cnt[ROWS];          // per-row count of strictly-greater sims
__device__ __half g_x1h[ROWS * KDIM];   // fp16 hi/lo split of inputs
__device__ __half g_x1l[ROWS * KDIM];
__device__ __half g_x2h[ROWS * KDIM];
__device__ __half g_x2l[ROWS * KDIM];

__device__ __forceinline__ uint32_t smem_u32(const void* p) {
    uint32_t a;
    asm("{ .reg .u64 t; cvta.to.shared.u64 t, %1; cvt.u32.u64 %0, t; }"
        : "=r"(a) : "l"(p));
    return a;
}

#define LDSM_X4(r0, r1, r2, r3, addr) \
    asm volatile("ldmatrix.sync.aligned.m8n8.x4.shared.b16 {%0,%1,%2,%3}, [%4];" \
                 : "=r"(r0), "=r"(r1), "=r"(r2), "=r"(r3) : "r"(addr))

#define MMA_16816(c, a, b0, b1) \
    asm volatile("mma.sync.aligned.m16n8k16.row.col.f32.f16.f16.f32 " \
                 "{%0,%1,%2,%3}, {%4,%5,%6,%7}, {%8,%9}, {%0,%1,%2,%3};" \
                 : "+f"((c)[0]), "+f"((c)[1]), "+f"((c)[2]), "+f"((c)[3]) \
                 : "r"((a)[0]), "r"((a)[1]), "r"((a)[2]), "r"((a)[3]), \
                   "r"(b0), "r"(b1))

#define CP_ASYNC16(dst, src) \
    asm volatile("cp.async.cg.shared.global [%0], [%1], 16;" :: "r"(dst), "l"(src))
#define CP_COMMIT() asm volatile("cp.async.commit_group;" ::: "memory")

// ---------------------------------------------------------------------------
// Kernel A: thresholds + counter zero + fp16 hi/lo conversion of both inputs.
// ---------------------------------------------------------------------------
__global__ void prep_kernel(const float* __restrict__ x1,
                            const float* __restrict__ x2) {
    int warp = (blockIdx.x * blockDim.x + threadIdx.x) >> 5;
    int lane = threadIdx.x & 31;
    if (warp >= ROWS) return;
    float4 a = *(const float4*)(x1 + warp * KDIM + lane * 4);
    float4 b = *(const float4*)(x2 + warp * KDIM + lane * 4);

    int base = warp * KDIM + lane * 4;
    {
        __half h0 = __float2half_rn(a.x), h1 = __float2half_rn(a.y);
        __half h2 = __float2half_rn(a.z), h3 = __float2half_rn(a.w);
        half2 H0 = __halves2half2(h0, h1), H1 = __halves2half2(h2, h3);
        uint2 hv = make_uint2(*(unsigned*)&H0, *(unsigned*)&H1);
        *(uint2*)(g_x1h + base) = hv;
        __half l0 = __float2half_rn(a.x - __half2float(h0));
        __half l1 = __float2half_rn(a.y - __half2float(h1));
        __half l2 = __float2half_rn(a.z - __half2float(h2));
        __half l3 = __float2half_rn(a.w - __half2float(h3));
        half2 L0 = __halves2half2(l0, l1), L1 = __halves2half2(l2, l3);
        uint2 lv = make_uint2(*(unsigned*)&L0, *(unsigned*)&L1);
        *(uint2*)(g_x1l + base) = lv;
    }
    {
        __half h0 = __float2half_rn(b.x), h1 = __float2half_rn(b.y);
        __half h2 = __float2half_rn(b.z), h3 = __float2half_rn(b.w);
        half2 H0 = __halves2half2(h0, h1), H1 = __halves2half2(h2, h3);
        uint2 hv = make_uint2(*(unsigned*)&H0, *(unsigned*)&H1);
        *(uint2*)(g_x2h + base) = hv;
        __half l0 = __float2half_rn(b.x - __half2float(h0));
        __half l1 = __float2half_rn(b.y - __half2float(h1));
        __half l2 = __float2half_rn(b.z - __half2float(h2));
        __half l3 = __float2half_rn(b.w - __half2float(h3));
        half2 L0 = __halves2half2(l0, l1), L1 = __halves2half2(l2, l3);
        uint2 lv = make_uint2(*(unsigned*)&L0, *(unsigned*)&L1);
        *(uint2*)(g_x2l + base) = lv;
    }

    float s2 = b.x * b.x + b.y * b.y + b.z * b.z + b.w * b.w;
    float d  = a.x * b.x + a.y * b.y + a.z * b.z + a.w * b.w;
    #pragma unroll
    for (int o = 16; o > 0; o >>= 1) {
        s2 += __shfl_down_sync(0xffffffffu, s2, o);
        d  += __shfl_down_sync(0xffffffffu, d,  o);
    }
    if (lane == 0) {
        float n2 = sqrtf(s2);
        g_n2[warp]  = n2;
        g_r[warp]   = d / n2;
        g_cnt[warp] = 0;
    }
}

// ---------------------------------------------------------------------------
// Kernel B: counting GEMM via mma.sync m16n8k16 fp16, 3-term hi/lo split.
// Tile BM=128 x BN=256, 512 threads (16 warps, 2x8), warp tile 64x32.
// Whole K=128 resident: 4 chunk-slabs of 48 KB (A_hi/A_lo 8K each,
// B_hi/B_lo 16K each), all cp.async issued up front, progressive wait.
// Row layout: 64B rows, 16B-slot swizzle slot ^= (row>>1)&3 (LDSM conflict-free).
// ---------------------------------------------------------------------------
#define CHUNK_SZ   49152
#define SMEM_TOTAL (4 * CHUNK_SZ)      // 192 KB

__device__ __forceinline__ void load_chunk(uint32_t bufb, int i0, int j0,
                                           int kc, int tid) {
    const int s  = tid & 3;            // 16B slot within 64B chunk-row
    const int rh = tid >> 2;           // 0..127
    const int swsh = ((s ^ ((rh >> 1) & 3)) << 4);
    // A_hi / A_lo: 128 rows
    CP_ASYNC16(bufb +         rh * 64 + swsh, g_x1h + (i0 + rh) * KDIM + kc + s * 8);
    CP_ASYNC16(bufb +  8192 + rh * 64 + swsh, g_x1l + (i0 + rh) * KDIM + kc + s * 8);
    // B_hi / B_lo: 256 rows (rh and rh+128)
    const int r2 = rh + 128;
    const int swsh2 = ((s ^ ((r2 >> 1) & 3)) << 4);
    CP_ASYNC16(bufb + 16384 + rh * 64 + swsh,  g_x2h + (j0 + rh) * KDIM + kc + s * 8);
    CP_ASYNC16(bufb + 16384 + r2 * 64 + swsh2, g_x2h + (j0 + r2) * KDIM + kc + s * 8);
    CP_ASYNC16(bufb + 32768 + rh * 64 + swsh,  g_x2l + (j0 + rh) * KDIM + kc + s * 8);
    CP_ASYNC16(bufb + 32768 + r2 * 64 + swsh2, g_x2l + (j0 + r2) * KDIM + kc + s * 8);
}

__device__ __forceinline__ void compute_chunk(uint32_t bufb, int wm, int wn,
                                              int l, float acc[4][4][4]) {
    const int lg = l >> 3, lr = l & 7;
    #pragma unroll
    for (int t = 0; t < 2; t++) {               // two k16 steps per chunk
        uint32_t ah[4][4], al[4][4];
        #pragma unroll
        for (int tm = 0; tm < 4; tm++) {
            const int row  = wm * 64 + tm * 16 + ((lg & 1) << 3) + lr;
            const int slot = 2 * t + (lg >> 1);
            const uint32_t off = row * 64 + ((slot ^ ((row >> 1) & 3)) << 4);
            LDSM_X4(ah[tm][0], ah[tm][1], ah[tm][2], ah[tm][3], bufb + off);
            LDSM_X4(al[tm][0], al[tm][1], al[tm][2], al[tm][3], bufb + 8192 + off);
        }
        #pragma unroll
        for (int p = 0; p < 2; p++) {           // n-tile pairs (2p, 2p+1)
            const int row  = wn * 32 + p * 16 + ((lg >> 1) << 3) + lr;
            const int slot = 2 * t + (lg & 1);
            const uint32_t off = row * 64 + ((slot ^ ((row >> 1) & 3)) << 4);
            uint32_t bh[4], bl[4];
            LDSM_X4(bh[0], bh[1], bh[2], bh[3], bufb + 16384 + off);
            LDSM_X4(bl[0], bl[1], bl[2], bl[3], bufb + 32768 + off);
            #pragma unroll
            for (int tm = 0; tm < 4; tm++) {
                MMA_16816(acc[tm][2 * p],     ah[tm], bh[0], bh[1]);
                MMA_16816(acc[tm][2 * p],     ah[tm], bl[0], bl[1]);
                MMA_16816(acc[tm][2 * p],     al[tm], bh[0], bh[1]);
                MMA_16816(acc[tm][2 * p + 1], ah[tm], bh[2], bh[3]);
                MMA_16816(acc[tm][2 * p + 1], ah[tm], bl[2], bl[3]);
                MMA_16816(acc[tm][2 * p + 1], al[tm], bh[2], bh[3]);
            }
        }
    }
}

__global__ __launch_bounds__(512, 1)
void count_kernel() {
    extern __shared__ char smem[];
    const uint32_t sb = smem_u32(smem);
    const int tid = threadIdx.x;
    const int l   = tid & 31;
    const int wid = tid >> 5;        // 0..15
    const int wm  = wid >> 3;        // 0..1  (64-row m slab)
    const int wn  = wid & 7;         // 0..7  (32-col n slab)
    const int i0  = blockIdx.y * 128;
    const int j0  = blockIdx.x * 256;

    // Issue ALL loads up front (24 cp.async groups of 1 chunk each in flight).
    #pragma unroll
    for (int c = 0; c < 4; c++) {
        load_chunk(sb + c * CHUNK_SZ, i0, j0, c * 32, tid);
        CP_COMMIT();
    }

    float acc[4][4][4];
    #pragma unroll
    for (int a = 0; a < 4; a++)
        #pragma unroll
        for (int b = 0; b < 4; b++)
            #pragma unroll
            for (int c = 0; c < 4; c++) acc[a][b][c] = 0.f;

    #pragma unroll
    for (int c = 0; c < 4; c++) {
        switch (c) {   // progressive completion: chunk c ready when <=3-c pending
            case 0: asm volatile("cp.async.wait_group 3;" ::: "memory"); break;
            case 1: asm volatile("cp.async.wait_group 2;" ::: "memory"); break;
            case 2: asm volatile("cp.async.wait_group 1;" ::: "memory"); break;
            default: asm volatile("cp.async.wait_group 0;" ::: "memory"); break;
        }
        __syncthreads();
        compute_chunk(sb + c * CHUNK_SZ, wm, wn, l, acc);
    }

    // Epilogue: compare dot > r_i * n2_j, exclude diagonal, count per row.
    float na[4], nb[4];
    #pragma unroll
    for (int tn = 0; tn < 4; tn++) {
        const int jb = j0 + wn * 32 + tn * 8 + ((l & 3) << 1);
        na[tn] = __ldg(&g_n2[jb]);
        nb[tn] = __ldg(&g_n2[jb + 1]);
    }
    #pragma unroll
    for (int tm = 0; tm < 4; tm++) {
        const int r0 = i0 + wm * 64 + tm * 16 + (l >> 2);
        const int r1 = r0 + 8;
        const float th0 = __ldg(&g_r[r0]);
        const float th1 = __ldg(&g_r[r1]);
        int c0 = 0, c1 = 0;
        #pragma unroll
        for (int tn = 0; tn < 4; tn++) {
            const int jb = j0 + wn * 32 + tn * 8 + ((l & 3) << 1);
            c0 += (acc[tm][tn][0] > th0 * na[tn] && jb     != r0) ? 1 : 0;
            c0 += (acc[tm][tn][1] > th0 * nb[tn] && jb + 1 != r0) ? 1 : 0;
            c1 += (acc[tm][tn][2] > th1 * na[tn] && jb     != r1) ? 1 : 0;
            c1 += (acc[tm][tn][3] > th1 * nb[tn] && jb + 1 != r1) ? 1 : 0;
        }
        c0 += __shfl_xor_sync(0xffffffffu, c0, 1);
        c0 += __shfl_xor_sync(0xffffffffu, c0, 2);
        c1 += __shfl_xor_sync(0xffffffffu, c1, 1);
        c1 += __shfl_xor_sync(0xffffffffu, c1, 2);
        if ((l & 3) == 0) {
            atomicAdd(&g_cnt[r0], c0);
            atomicAdd(&g_cnt[r1], c1);
        }
    }
}

// ---------------------------------------------------------------------------
// Kernel C: mean of (count < NPER)
// ---------------------------------------------------------------------------
__global__ void finalize_kernel(float* __restrict__ out) {
    __shared__ int sh[256];
    int t = threadIdx.x;
    int c = 0;
    for (int i = t; i < ROWS; i += 256) c += (g_cnt[i] < NPER) ? 1 : 0;
    sh[t] = c;
    __syncthreads();
    #pragma unroll
    for (int s = 128; s > 0; s >>= 1) {
        if (t < s) sh[t] += sh[t + s];
        __syncthreads();
    }
    if (t == 0) out[0] = (float)sh[0] / (float)ROWS;
}

// ---------------------------------------------------------------------------
extern "C" void kernel_launch(void* const* d_in, const int* in_sizes, int n_in,
                              void* d_out, int out_size) {
    const float* x1 = (const float*)d_in[0];
    const float* x2 = (const float*)d_in[1];
    float* out = (float*)d_out;
    (void)in_sizes; (void)n_in; (void)out_size;

    cudaFuncSetAttribute(count_kernel,
                         cudaFuncAttributeMaxDynamicSharedMemorySize, SMEM_TOTAL);

    prep_kernel<<<ROWS / 8, 256>>>(x1, x2);
    count_kernel<<<dim3(32, 64), 512, SMEM_TOTAL>>>();
    finalize_kernel<<<1, 256>>>(out);
}